// round 7
// baseline (speedup 1.0000x reference)
#include <cuda_runtime.h>
#include <cstdint>

#define NB    8
#define NPB   8192
#define FDIM  64
#define MQ    2048
#define KNN   32
#define CDIM  128
#define R2C   0.01f
#define NROWS (NB*NPB)
#define CAP   256
#define FULLM 0xffffffffu
#define NWORK 128

// scratch (device globals — no allocation allowed)
__device__ float g_xw[(size_t)NROWS * CDIM];   // x @ W1[0:64]
__device__ float g_qpos[NB * MQ * 3];
__device__ unsigned g_prog[NB];                // samples emitted per cloud (monotone)
__device__ unsigned g_xwdone;                  // workers done with xw (monotone)

// ---- packed f32x2 helpers (sm_103a) --------------------------------
__device__ __forceinline__ unsigned long long pk2(float lo, float hi) {
    unsigned long long r;
    asm("mov.b64 %0, {%1,%2};" : "=l"(r) : "f"(lo), "f"(hi));
    return r;
}
__device__ __forceinline__ void upk2(float& lo, float& hi, unsigned long long v) {
    asm("mov.b64 {%0,%1}, %2;" : "=f"(lo), "=f"(hi) : "l"(v));
}
#define ADD2(o,a,b)   asm("add.rn.f32x2 %0, %1, %2;"     : "=l"(o) : "l"(a), "l"(b))
#define MUL2(o,a,b)   asm("mul.rn.f32x2 %0, %1, %2;"     : "=l"(o) : "l"(a), "l"(b))
#define FMA2(o,a,b,c) asm("fma.rn.f32x2 %0, %1, %2, %3;" : "=l"(o) : "l"(a), "l"(b), "l"(c))

__device__ __forceinline__ unsigned ld_acq(const unsigned* p) {
    unsigned v;
    asm volatile("ld.acquire.gpu.u32 %0, [%1];" : "=r"(v) : "l"(p));
    return v;
}
__device__ __forceinline__ void st_rel(unsigned* p, unsigned v) {
    asm volatile("st.release.gpu.u32 [%0], %1;" :: "l"(p), "r"(v));
}

// ------------------------------------------------------------------
// ONE persistent kernel, 136 CTAs (all co-resident on 148 SMs):
//   blocks [0,8):    FPS, one CTA per cloud (serial argmax chain)
//   blocks [8,136):  workers — xW slice, then ballconv gated on FPS progress
// ------------------------------------------------------------------
__global__ void __launch_bounds__(1024, 1)
sa_fused_kernel(const float* __restrict__ pos, const float* __restrict__ x,
                const float* __restrict__ W1, const float* __restrict__ b1,
                float* __restrict__ dout, int extras)
{
    extern __shared__ float sm[];
    const int tid = threadIdx.x;
    const int warp = tid >> 5, lane = tid & 31;

    const long long OQ = (long long)NB * MQ * CDIM;
    const long long OB = OQ + (long long)NB * MQ * 3;
    const long long OI = OB + (long long)NB * MQ;

    if (blockIdx.x < NB) {
        // ============ FPS branch ============
        const int b = blockIdx.x;
        const float* pb = pos + (size_t)b * NPB * 3;

        float* sx = sm;
        float* sy = sx + NPB;
        float* sz = sy + NPB;
        unsigned long long* skey = (unsigned long long*)(sz + NPB);

        for (int i = tid; i < NPB * 3; i += 1024) {
            float v = pb[i];
            int pt = i / 3, c = i - pt * 3;
            if (c == 0) sx[pt] = v; else if (c == 1) sy[pt] = v; else sz[pt] = v;
        }
        if (tid == 0) *skey = 0ull;
        __syncthreads();

        unsigned long long pxp[4], pyp[4], pzp[4];
        float dmin[8];
#pragma unroll
        for (int p = 0; p < 4; p++) {
            int i0 = tid + (2 * p) * 1024, i1 = tid + (2 * p + 1) * 1024;
            pxp[p] = pk2(sx[i0], sx[i1]);
            pyp[p] = pk2(sy[i0], sy[i1]);
            pzp[p] = pk2(sz[i0], sz[i1]);
            dmin[2 * p] = 3.4e38f; dmin[2 * p + 1] = 3.4e38f;
        }

        float qx = sx[0], qy = sy[0], qz = sz[0];
        if (tid == 0) {
            int row = b * MQ;
            g_qpos[row * 3 + 0] = qx; g_qpos[row * 3 + 1] = qy; g_qpos[row * 3 + 2] = qz;
            if (extras) {
                dout[OQ + row * 3 + 0] = qx;
                dout[OQ + row * 3 + 1] = qy;
                dout[OQ + row * 3 + 2] = qz;
                dout[OB + row] = (float)b;
                dout[OI + row] = (float)(b * NPB);
            }
            st_rel(&g_prog[b], 1u);
        }

        volatile unsigned long long* vkey = skey;

        for (int m = 1; m < MQ; m++) {
            unsigned long long nqx2 = pk2(-qx, -qx);
            unsigned long long nqy2 = pk2(-qy, -qy);
            unsigned long long nqz2 = pk2(-qz, -qz);
#pragma unroll
            for (int p = 0; p < 4; p++) {
                unsigned long long dx, dy, dz, t;
                ADD2(dx, pxp[p], nqx2);
                ADD2(dy, pyp[p], nqy2);
                ADD2(dz, pzp[p], nqz2);
                MUL2(t, dx, dx);
                FMA2(t, dy, dy, t);
                FMA2(t, dz, dz, t);          // ((dx*dx + dy*dy) + dz*dz), per-lane IEEE
                float lo, hi; upk2(lo, hi, t);
                dmin[2 * p]     = fminf(dmin[2 * p],     lo);
                dmin[2 * p + 1] = fminf(dmin[2 * p + 1], hi);
            }

            // per-thread argmax; strict > keeps the LOWEST index among ties
            float bv = dmin[0];
            int bidx = tid;
#pragma unroll
            for (int k = 1; k < 8; k++) {
                bidx = (dmin[k] > bv) ? (tid + k * 1024) : bidx;
                bv = fmaxf(bv, dmin[k]);
            }

            unsigned vb = __float_as_uint(bv);
            unsigned wmax = __reduce_max_sync(FULLM, vb);

            // block argmax: step-tagged 64-bit key, stale entries always lose
            if (vb == wmax) {
                unsigned long long key = ((unsigned long long)m << 44)
                                       | ((unsigned long long)wmax << 13)
                                       | (unsigned long long)(8191 - bidx);
                atomicMax((unsigned long long*)skey, key);
            }
            __syncthreads();                 // drains shared atomics

            unsigned long long kk = *vkey;
            int win = 8191 - (int)(kk & 0x1fffull);
            qx = sx[win]; qy = sy[win]; qz = sz[win];

            if (tid == 0) {
                int row = b * MQ + m;
                g_qpos[row * 3 + 0] = qx; g_qpos[row * 3 + 1] = qy; g_qpos[row * 3 + 2] = qz;
                if (extras) {
                    dout[OQ + row * 3 + 0] = qx;
                    dout[OQ + row * 3 + 1] = qy;
                    dout[OQ + row * 3 + 2] = qz;
                    dout[OB + row] = (float)b;
                    dout[OI + row] = (float)(b * NPB + win);
                }
                st_rel(&g_prog[b], (unsigned)(m + 1));
            }
        }
        return;
    }

    // ============ worker branch ============
    const int w = blockIdx.x - NB;           // 0..127

    // ---- phase 1: xW slice (512 rows) ----
    {
        float* Wf = sm;                      // 64*128 floats = 32KB
        for (int i = tid; i < 64 * CDIM / 4; i += 1024)
            ((float4*)Wf)[i] = ((const float4*)W1)[i];
        __syncthreads();

        const int rbase = w * 512 + warp * 16;
        for (int p = 0; p < 8; p++) {
            int r0 = rbase + p * 2, r1 = r0 + 1;
            float2 a = ((const float2*)(x + (size_t)r0 * FDIM))[lane];
            float2 c = ((const float2*)(x + (size_t)r1 * FDIM))[lane];
            float4 a0 = make_float4(0.f, 0.f, 0.f, 0.f);
            float4 a1 = make_float4(0.f, 0.f, 0.f, 0.f);
#pragma unroll
            for (int k2 = 0; k2 < 32; k2++) {
                float xa0 = __shfl_sync(FULLM, a.x, k2);
                float xa1 = __shfl_sync(FULLM, a.y, k2);
                float xc0 = __shfl_sync(FULLM, c.x, k2);
                float xc1 = __shfl_sync(FULLM, c.y, k2);
                float4 w0 = ((float4*)(Wf + (2 * k2) * CDIM))[lane];
                float4 w1 = ((float4*)(Wf + (2 * k2 + 1) * CDIM))[lane];
                a0.x = fmaf(xa0, w0.x, a0.x); a0.y = fmaf(xa0, w0.y, a0.y);
                a0.z = fmaf(xa0, w0.z, a0.z); a0.w = fmaf(xa0, w0.w, a0.w);
                a0.x = fmaf(xa1, w1.x, a0.x); a0.y = fmaf(xa1, w1.y, a0.y);
                a0.z = fmaf(xa1, w1.z, a0.z); a0.w = fmaf(xa1, w1.w, a0.w);
                a1.x = fmaf(xc0, w0.x, a1.x); a1.y = fmaf(xc0, w0.y, a1.y);
                a1.z = fmaf(xc0, w0.z, a1.z); a1.w = fmaf(xc0, w0.w, a1.w);
                a1.x = fmaf(xc1, w1.x, a1.x); a1.y = fmaf(xc1, w1.y, a1.y);
                a1.z = fmaf(xc1, w1.z, a1.z); a1.w = fmaf(xc1, w1.w, a1.w);
            }
            ((float4*)(g_xw + (size_t)r0 * CDIM))[lane] = a0;
            ((float4*)(g_xw + (size_t)r1 * CDIM))[lane] = a1;
        }
        __syncthreads();                     // done using Wf region
        if (tid == 0) {
            __threadfence();
            atomicAdd(&g_xwdone, 1u);
        }
    }

    // ---- phase 2: ballconv, gated on FPS progress ----
    const int b   = w >> 4;                  // 16 workers per cloud
    const int sub = w & 15;                  // 128 queries per worker
    const float* pb = pos + (size_t)b * NPB * 3;

    float* spx = sm;
    float* spy = spx + NPB;
    float* spz = spy + NPB;
    unsigned long long* skey = (unsigned long long*)(spz + NPB);   // 32 warps * CAP
    int* ssel = (int*)(skey + 32 * CAP);                           // 32 warps * KNN

    for (int i = tid; i < NPB * 3; i += 1024) {
        float v = pb[i];
        int pt = i / 3, c = i - pt * 3;
        if (c == 0) spx[pt] = v; else if (c == 1) spy[pt] = v; else spz[pt] = v;
    }

    float4 wp0 = *(const float4*)(W1 + 64 * CDIM + 4 * lane);
    float4 wp1 = *(const float4*)(W1 + 65 * CDIM + 4 * lane);
    float4 wp2 = *(const float4*)(W1 + 66 * CDIM + 4 * lane);
    float4 bb  = *(const float4*)(b1 + 4 * lane);
    __syncthreads();

    // all 128 workers must have finished xw before we read g_xw
    while (ld_acq(&g_xwdone) < (unsigned)NWORK) __nanosleep(256);
    __threadfence();

    unsigned long long* mykey = skey + warp * CAP;
    int* mysel = ssel + warp * KNN;
    const unsigned ltmask = (1u << lane) - 1u;
    const int qbase = sub * 128 + warp * 4;  // 4 queries per warp, contiguous

    for (int qi = 0; qi < 4; qi++) {
        int m = qbase + qi;
        int row = b * MQ + m;

        // wait until FPS has emitted sample m (acquire pairs with FPS release)
        while (ld_acq(&g_prog[b]) <= (unsigned)m) __nanosleep(128);

        float qx = g_qpos[row * 3 + 0];
        float qy = g_qpos[row * 3 + 1];
        float qz = g_qpos[row * 3 + 2];

        int cnt = 0;
        for (int t = 0; t < NPB / 32; t++) {
            int i = lane + t * 32;
            float dx = spx[i] - qx, dy = spy[i] - qy, dz = spz[i] - qz;
            float d2 = fmaf(dz, dz, fmaf(dy, dy, dx * dx));
            bool in = (d2 <= R2C);
            unsigned mk = __ballot_sync(FULLM, in);
            if (in) {
                int off = cnt + __popc(mk & ltmask);
                if (off < CAP)
                    mykey[off] = ((unsigned long long)__float_as_uint(d2) << 32) | (unsigned)i;
            }
            cnt += __popc(mk);
        }
        if (cnt > CAP) cnt = CAP;

        int nsel;
        if (cnt <= KNN) {
            nsel = cnt;
            if (lane < cnt) mysel[lane] = (int)(mykey[lane] & 0xffffffffull);
        } else {
            nsel = KNN;
            int written = 0;
            for (int base = 0; base < cnt; base += 32) {
                int c = base + lane;
                bool s = false;
                unsigned long long ka = 0ull;
                if (c < cnt) {
                    ka = mykey[c];
                    int rank = 0;
                    for (int e = 0; e < cnt; e++) rank += (mykey[e] < ka) ? 1 : 0;
                    s = (rank < KNN);
                }
                unsigned mk = __ballot_sync(FULLM, s);
                if (s) mysel[written + __popc(mk & ltmask)] = (int)(ka & 0xffffffffull);
                written += __popc(mk);
            }
        }
        __syncwarp();

        float4 vm = make_float4(-3.4e38f, -3.4e38f, -3.4e38f, -3.4e38f);
        for (int s = 0; s < nsel; s++) {
            int j = mysel[s];
            float dx = spx[j] - qx, dy = spy[j] - qy, dz = spz[j] - qz;
            float4 xw = *(const float4*)(g_xw + (size_t)(b * NPB + j) * CDIM + 4 * lane);
            float v0 = fmaf(dz, wp2.x, fmaf(dy, wp1.x, fmaf(dx, wp0.x, xw.x)));
            float v1 = fmaf(dz, wp2.y, fmaf(dy, wp1.y, fmaf(dx, wp0.y, xw.y)));
            float v2 = fmaf(dz, wp2.z, fmaf(dy, wp1.z, fmaf(dx, wp0.z, xw.z)));
            float v3 = fmaf(dz, wp2.w, fmaf(dy, wp1.w, fmaf(dx, wp0.w, xw.w)));
            vm.x = fmaxf(vm.x, v0); vm.y = fmaxf(vm.y, v1);
            vm.z = fmaxf(vm.z, v2); vm.w = fmaxf(vm.w, v3);
        }
        float4 o;
        o.x = fmaxf(vm.x + bb.x, 0.0f);
        o.y = fmaxf(vm.y + bb.y, 0.0f);
        o.z = fmaxf(vm.z + bb.z, 0.0f);
        o.w = fmaxf(vm.w + bb.w, 0.0f);
        *(float4*)(dout + (size_t)row * CDIM + 4 * lane) = o;
        __syncwarp();
    }
}

// ------------------------------------------------------------------
extern "C" void kernel_launch(void* const* d_in, const int* in_sizes, int n_in,
                              void* d_out, int out_size)
{
    const float *x = nullptr, *pos = nullptr, *W1 = nullptr, *b1 = nullptr;
    for (int i = 0; i < n_in; i++) {
        switch (in_sizes[i]) {
            case NROWS * FDIM:      x   = (const float*)d_in[i]; break;
            case NROWS * 3:         pos = (const float*)d_in[i]; break;
            case (FDIM + 3) * CDIM: W1  = (const float*)d_in[i]; break;
            case CDIM:              b1  = (const float*)d_in[i]; break;
            default: break;                                        // batch (unused)
        }
    }
    float* out = (float*)d_out;
    long long total = (long long)NB * MQ * CDIM + (long long)NB * MQ * 3 + 2ll * NB * MQ;
    int extras = ((long long)out_size >= total) ? 1 : 0;

    // smem: positions (96KB) + 32-warp candidate keys (64KB) + sel (4KB)
    size_t smem = (size_t)3 * NPB * 4 + (size_t)32 * CAP * 8 + (size_t)32 * KNN * 4; // 167936
    cudaFuncSetAttribute(sa_fused_kernel, cudaFuncAttributeMaxDynamicSharedMemorySize, (int)smem);
    sa_fused_kernel<<<NB + NWORK, 1024, smem>>>(pos, x, W1, b1, out, extras);
}

// round 11
// speedup vs baseline: 1.0978x; 1.0978x over previous
#include <cuda_runtime.h>
#include <cstdint>

#define NB    8
#define NPB   8192
#define FDIM  64
#define MQ    2048
#define KNN   32
#define CDIM  128
#define R2C   0.01f
#define NROWS (NB*NPB)
#define CAP   256
#define FULLM 0xffffffffu

// scratch (device globals — no allocation allowed)
__device__ float g_xw[(size_t)NROWS * CDIM];   // x @ W1[0:64]
__device__ float g_qpos[NB * MQ * 3];

// ---- packed f32x2 helpers (sm_103a; only add/mul/fma exist packed) ----
__device__ __forceinline__ unsigned long long pk2(float lo, float hi) {
    unsigned long long r;
    asm("mov.b64 %0, {%1,%2};" : "=l"(r) : "f"(lo), "f"(hi));
    return r;
}
__device__ __forceinline__ void upk2(float& lo, float& hi, unsigned long long v) {
    asm("mov.b64 {%0,%1}, %2;" : "=f"(lo), "=f"(hi) : "l"(v));
}
#define ADD2(o,a,b)   asm("add.rn.f32x2 %0, %1, %2;"     : "=l"(o) : "l"(a), "l"(b))
#define MUL2(o,a,b)   asm("mul.rn.f32x2 %0, %1, %2;"     : "=l"(o) : "l"(a), "l"(b))
#define FMA2(o,a,b,c) asm("fma.rn.f32x2 %0, %1, %2, %3;" : "=l"(o) : "l"(a), "l"(b), "l"(c))

// ------------------------------------------------------------------
// Fused kernel: blocks [0,NB) run FPS (serial chain, 1 CTA/cloud),
// blocks [NB, NB+128) run xW = x @ W1[0:64] on the other SMs.
// ------------------------------------------------------------------
__global__ void __launch_bounds__(1024, 1)
fps_xw_kernel(const float* __restrict__ pos, const float* __restrict__ x,
              const float* __restrict__ W1, float* __restrict__ dout, int extras)
{
    extern __shared__ float sm[];
    const int tid = threadIdx.x;

    if (blockIdx.x >= NB) {
        // ------------------ xW GEMM branch ------------------
        float* Wf = sm;                      // 64*128 floats = 32KB
        for (int i = tid; i < 64 * CDIM / 4; i += 1024)
            ((float4*)Wf)[i] = ((const float4*)W1)[i];
        __syncthreads();

        const int warp = tid >> 5, lane = tid & 31;
        const int rbase = (blockIdx.x - NB) * 512 + warp * 16;

        for (int p = 0; p < 8; p++) {
            int r0 = rbase + p * 2, r1 = r0 + 1;
            float2 a = ((const float2*)(x + (size_t)r0 * FDIM))[lane];
            float2 c = ((const float2*)(x + (size_t)r1 * FDIM))[lane];
            float4 a0 = make_float4(0.f, 0.f, 0.f, 0.f);
            float4 a1 = make_float4(0.f, 0.f, 0.f, 0.f);
#pragma unroll
            for (int k2 = 0; k2 < 32; k2++) {
                float xa0 = __shfl_sync(FULLM, a.x, k2);
                float xa1 = __shfl_sync(FULLM, a.y, k2);
                float xc0 = __shfl_sync(FULLM, c.x, k2);
                float xc1 = __shfl_sync(FULLM, c.y, k2);
                float4 w0 = ((float4*)(Wf + (2 * k2) * CDIM))[lane];
                float4 w1 = ((float4*)(Wf + (2 * k2 + 1) * CDIM))[lane];
                a0.x = fmaf(xa0, w0.x, a0.x); a0.y = fmaf(xa0, w0.y, a0.y);
                a0.z = fmaf(xa0, w0.z, a0.z); a0.w = fmaf(xa0, w0.w, a0.w);
                a0.x = fmaf(xa1, w1.x, a0.x); a0.y = fmaf(xa1, w1.y, a0.y);
                a0.z = fmaf(xa1, w1.z, a0.z); a0.w = fmaf(xa1, w1.w, a0.w);
                a1.x = fmaf(xc0, w0.x, a1.x); a1.y = fmaf(xc0, w0.y, a1.y);
                a1.z = fmaf(xc0, w0.z, a1.z); a1.w = fmaf(xc0, w0.w, a1.w);
                a1.x = fmaf(xc1, w1.x, a1.x); a1.y = fmaf(xc1, w1.y, a1.y);
                a1.z = fmaf(xc1, w1.z, a1.z); a1.w = fmaf(xc1, w1.w, a1.w);
            }
            ((float4*)(g_xw + (size_t)r0 * CDIM))[lane] = a0;
            ((float4*)(g_xw + (size_t)r1 * CDIM))[lane] = a1;
        }
        return;
    }

    // ------------------ FPS branch ------------------
    const int b = blockIdx.x;
    const float* pb = pos + (size_t)b * NPB * 3;

    float* sx = sm;
    float* sy = sx + NPB;
    float* sz = sy + NPB;
    unsigned long long* skey = (unsigned long long*)(sz + NPB);   // single accumulator

    for (int i = tid; i < NPB * 3; i += 1024) {
        float v = pb[i];
        int pt = i / 3, c = i - pt * 3;
        if (c == 0) sx[pt] = v; else if (c == 1) sy[pt] = v; else sz[pt] = v;
    }
    if (tid == 0) *skey = 0ull;
    __syncthreads();

    // pair p holds point slots tid+2p*1024 (lo) and tid+(2p+1)*1024 (hi)
    unsigned long long pxp[4], pyp[4], pzp[4];
    float dmin[8];
#pragma unroll
    for (int p = 0; p < 4; p++) {
        int i0 = tid + (2 * p) * 1024, i1 = tid + (2 * p + 1) * 1024;
        pxp[p] = pk2(sx[i0], sx[i1]);
        pyp[p] = pk2(sy[i0], sy[i1]);
        pzp[p] = pk2(sz[i0], sz[i1]);
        dmin[2 * p] = 3.4e38f; dmin[2 * p + 1] = 3.4e38f;
    }

    const long long OQ = (long long)NB * MQ * CDIM;
    const long long OB = OQ + (long long)NB * MQ * 3;
    const long long OI = OB + (long long)NB * MQ;

    float qx = sx[0], qy = sy[0], qz = sz[0];
    if (tid == 0) {
        int row = b * MQ;
        g_qpos[row * 3 + 0] = qx; g_qpos[row * 3 + 1] = qy; g_qpos[row * 3 + 2] = qz;
        if (extras) {
            dout[OQ + row * 3 + 0] = qx;
            dout[OQ + row * 3 + 1] = qy;
            dout[OQ + row * 3 + 2] = qz;
            dout[OB + row] = (float)b;
            dout[OI + row] = (float)(b * NPB);
        }
    }

    volatile unsigned long long* vkey = skey;

    for (int m = 1; m < MQ; m++) {
        unsigned long long nqx2 = pk2(-qx, -qx);
        unsigned long long nqy2 = pk2(-qy, -qy);
        unsigned long long nqz2 = pk2(-qz, -qz);
#pragma unroll
        for (int p = 0; p < 4; p++) {
            unsigned long long dx, dy, dz, t;
            ADD2(dx, pxp[p], nqx2);
            ADD2(dy, pyp[p], nqy2);
            ADD2(dz, pzp[p], nqz2);
            MUL2(t, dx, dx);
            FMA2(t, dy, dy, t);
            FMA2(t, dz, dz, t);              // ((dx*dx + dy*dy) + dz*dz), per-lane IEEE
            float lo, hi; upk2(lo, hi, t);
            dmin[2 * p]     = fminf(dmin[2 * p],     lo);
            dmin[2 * p + 1] = fminf(dmin[2 * p + 1], hi);
        }

        // value-only max tree (FMNMX, bit-exact)
        float m01 = fmaxf(dmin[0], dmin[1]), m23 = fmaxf(dmin[2], dmin[3]);
        float m45 = fmaxf(dmin[4], dmin[5]), m67 = fmaxf(dmin[6], dmin[7]);
        float bv = fmaxf(fmaxf(m01, m23), fmaxf(m45, m67));

        // warp/block max via single 32-bit REDUX (nonneg float bits monotone)
        unsigned vb = __float_as_uint(bv);
        unsigned wmax = __reduce_max_sync(FULLM, vb);

        // lazy index search: only tied threads scan their 8 slots
        // (descending k -> lowest global index wins, first-occurrence semantics)
        if (vb == wmax) {
            int bidx = tid;
#pragma unroll
            for (int k = 7; k >= 0; k--)
                if (__float_as_uint(dmin[k]) == wmax) bidx = tid + k * 1024;
            unsigned long long key = ((unsigned long long)m << 44)
                                   | ((unsigned long long)wmax << 13)
                                   | (unsigned long long)(8191 - bidx);
            atomicMax((unsigned long long*)skey, key);
        }
        __syncthreads();                     // drains shared atomics

        unsigned long long kk = *vkey;
        int win = 8191 - (int)(kk & 0x1fffull);
        qx = sx[win]; qy = sy[win]; qz = sz[win];

        if (tid == 0) {
            int row = b * MQ + m;
            g_qpos[row * 3 + 0] = qx; g_qpos[row * 3 + 1] = qy; g_qpos[row * 3 + 2] = qz;
            if (extras) {
                dout[OQ + row * 3 + 0] = qx;
                dout[OQ + row * 3 + 1] = qy;
                dout[OQ + row * 3 + 2] = qz;
                dout[OB + row] = (float)b;
                dout[OI + row] = (float)(b * NPB + win);
            }
        }
    }
}

// ------------------------------------------------------------------
// Ball query (exact top-K set) + fused pos-MLP + max + relu
// grid 128 (16 CTAs/cloud), 1024 threads (32 warps); each warp: 4 queries
// ------------------------------------------------------------------
__global__ void __launch_bounds__(1024)
ballconv_kernel(const float* __restrict__ pos, const float* __restrict__ W1,
                const float* __restrict__ b1, float* __restrict__ dout)
{
    extern __shared__ float smem[];
    float* spx = smem;
    float* spy = spx + NPB;
    float* spz = spy + NPB;
    unsigned long long* skey = (unsigned long long*)(spz + NPB);   // 32 warps * CAP
    int* ssel = (int*)(skey + 32 * CAP);                           // 32 warps * KNN

    const int b   = blockIdx.x >> 4;
    const int sub = blockIdx.x & 15;
    const int tid = threadIdx.x, warp = tid >> 5, lane = tid & 31;
    const float* pb = pos + (size_t)b * NPB * 3;

    for (int i = tid; i < NPB * 3; i += 1024) {
        float v = pb[i];
        int pt = i / 3, c = i - pt * 3;
        if (c == 0) spx[pt] = v; else if (c == 1) spy[pt] = v; else spz[pt] = v;
    }

    float4 wp0 = *(const float4*)(W1 + 64 * CDIM + 4 * lane);
    float4 wp1 = *(const float4*)(W1 + 65 * CDIM + 4 * lane);
    float4 wp2 = *(const float4*)(W1 + 66 * CDIM + 4 * lane);
    float4 bb  = *(const float4*)(b1 + 4 * lane);
    __syncthreads();

    unsigned long long* mykey = skey + warp * CAP;
    int* mysel = ssel + warp * KNN;
    const unsigned ltmask = (1u << lane) - 1u;
    const int qbase = sub * 128 + warp * 4;

    for (int qi = 0; qi < 4; qi++) {
        int m = qbase + qi;
        int row = b * MQ + m;
        float qx = g_qpos[row * 3 + 0];
        float qy = g_qpos[row * 3 + 1];
        float qz = g_qpos[row * 3 + 2];
        unsigned long long nqx2 = pk2(-qx, -qx);
        unsigned long long nqy2 = pk2(-qy, -qy);
        unsigned long long nqz2 = pk2(-qz, -qz);

        // packed scan: 2 points per lane per iter (same IEEE contraction as ref)
        int cnt = 0;
        for (int t = 0; t < NPB / 64; t++) {
            int i0 = t * 64 + lane, i1 = i0 + 32;
            unsigned long long ppx = pk2(spx[i0], spx[i1]);
            unsigned long long ppy = pk2(spy[i0], spy[i1]);
            unsigned long long ppz = pk2(spz[i0], spz[i1]);
            unsigned long long dx, dy, dz, d2p;
            ADD2(dx, ppx, nqx2);
            ADD2(dy, ppy, nqy2);
            ADD2(dz, ppz, nqz2);
            MUL2(d2p, dx, dx);
            FMA2(d2p, dy, dy, d2p);
            FMA2(d2p, dz, dz, d2p);
            float d2a, d2b; upk2(d2a, d2b, d2p);
            bool in0 = (d2a <= R2C), in1 = (d2b <= R2C);
            unsigned mk0 = __ballot_sync(FULLM, in0);
            unsigned mk1 = __ballot_sync(FULLM, in1);
            if (in0) {
                int off = cnt + __popc(mk0 & ltmask);
                if (off < CAP)
                    mykey[off] = ((unsigned long long)__float_as_uint(d2a) << 32) | (unsigned)i0;
            }
            cnt += __popc(mk0);
            if (in1) {
                int off = cnt + __popc(mk1 & ltmask);
                if (off < CAP)
                    mykey[off] = ((unsigned long long)__float_as_uint(d2b) << 32) | (unsigned)i1;
            }
            cnt += __popc(mk1);
        }
        if (cnt > CAP) cnt = CAP;

        int nsel;
        if (cnt <= KNN) {
            nsel = cnt;
            if (lane < cnt) mysel[lane] = (int)(mykey[lane] & 0xffffffffull);
        } else {
            nsel = KNN;
            int written = 0;
            for (int base = 0; base < cnt; base += 32) {
                int c = base + lane;
                bool s = false;
                unsigned long long ka = 0ull;
                if (c < cnt) {
                    ka = mykey[c];
                    int rank = 0;
                    for (int e = 0; e < cnt; e++) rank += (mykey[e] < ka) ? 1 : 0;
                    s = (rank < KNN);
                }
                unsigned mk = __ballot_sync(FULLM, s);
                if (s) mysel[written + __popc(mk & ltmask)] = (int)(ka & 0xffffffffull);
                written += __popc(mk);
            }
        }
        __syncwarp();

        float4 vm = make_float4(-3.4e38f, -3.4e38f, -3.4e38f, -3.4e38f);
        for (int s = 0; s < nsel; s++) {
            int j = mysel[s];
            float dx = spx[j] - qx, dy = spy[j] - qy, dz = spz[j] - qz;
            float4 xw = *(const float4*)(g_xw + (size_t)(b * NPB + j) * CDIM + 4 * lane);
            float v0 = fmaf(dz, wp2.x, fmaf(dy, wp1.x, fmaf(dx, wp0.x, xw.x)));
            float v1 = fmaf(dz, wp2.y, fmaf(dy, wp1.y, fmaf(dx, wp0.y, xw.y)));
            float v2 = fmaf(dz, wp2.z, fmaf(dy, wp1.z, fmaf(dx, wp0.z, xw.z)));
            float v3 = fmaf(dz, wp2.w, fmaf(dy, wp1.w, fmaf(dx, wp0.w, xw.w)));
            vm.x = fmaxf(vm.x, v0); vm.y = fmaxf(vm.y, v1);
            vm.z = fmaxf(vm.z, v2); vm.w = fmaxf(vm.w, v3);
        }
        float4 o;
        o.x = fmaxf(vm.x + bb.x, 0.0f);
        o.y = fmaxf(vm.y + bb.y, 0.0f);
        o.z = fmaxf(vm.z + bb.z, 0.0f);
        o.w = fmaxf(vm.w + bb.w, 0.0f);
        *(float4*)(dout + (size_t)row * CDIM + 4 * lane) = o;
        __syncwarp();
    }
}

// ------------------------------------------------------------------
extern "C" void kernel_launch(void* const* d_in, const int* in_sizes, int n_in,
                              void* d_out, int out_size)
{
    const float *x = nullptr, *pos = nullptr, *W1 = nullptr, *b1 = nullptr;
    for (int i = 0; i < n_in; i++) {
        switch (in_sizes[i]) {
            case NROWS * FDIM:      x   = (const float*)d_in[i]; break;
            case NROWS * 3:         pos = (const float*)d_in[i]; break;
            case (FDIM + 3) * CDIM: W1  = (const float*)d_in[i]; break;
            case CDIM:              b1  = (const float*)d_in[i]; break;
            default: break;                                        // batch (unused)
        }
    }
    float* out = (float*)d_out;
    long long total = (long long)NB * MQ * CDIM + (long long)NB * MQ * 3 + 2ll * NB * MQ;
    int extras = ((long long)out_size >= total) ? 1 : 0;

    size_t smem1 = (size_t)3 * NPB * 4 + 16;                       // ~96 KB + key
    cudaFuncSetAttribute(fps_xw_kernel, cudaFuncAttributeMaxDynamicSharedMemorySize, (int)smem1);
    fps_xw_kernel<<<NB + 128, 1024, smem1>>>(pos, x, W1, out, extras);

    // 96KB positions + 64KB candidate keys (32 warps) + 4KB sel
    size_t smem2 = (size_t)3 * NPB * 4 + (size_t)32 * CAP * 8 + (size_t)32 * KNN * 4; // 167936
    cudaFuncSetAttribute(ballconv_kernel, cudaFuncAttributeMaxDynamicSharedMemorySize, (int)smem2);
    ballconv_kernel<<<128, 1024, smem2>>>(pos, W1, b1, out);
}

// round 13
// speedup vs baseline: 1.2312x; 1.1215x over previous
#include <cuda_runtime.h>
#include <cstdint>

#define NB    8
#define NPB   8192
#define FDIM  64
#define MQ    2048
#define KNN   32
#define CDIM  128
#define R2C   0.01f
#define NROWS (NB*NPB)
#define CAP   256
#define FULLM 0xffffffffu

// scratch (device globals — no allocation allowed)
__device__ float g_xw[(size_t)NROWS * CDIM];   // x @ W1[0:64]
__device__ float g_qpos[NB * MQ * 3];

// ---- packed f32x2 helpers (sm_103a; only add/mul/fma exist packed) ----
__device__ __forceinline__ unsigned long long pk2(float lo, float hi) {
    unsigned long long r;
    asm("mov.b64 %0, {%1,%2};" : "=l"(r) : "f"(lo), "f"(hi));
    return r;
}
__device__ __forceinline__ void upk2(float& lo, float& hi, unsigned long long v) {
    asm("mov.b64 {%0,%1}, %2;" : "=f"(lo), "=f"(hi) : "l"(v));
}
#define ADD2(o,a,b)   asm("add.rn.f32x2 %0, %1, %2;"     : "=l"(o) : "l"(a), "l"(b))
#define MUL2(o,a,b)   asm("mul.rn.f32x2 %0, %1, %2;"     : "=l"(o) : "l"(a), "l"(b))
#define FMA2(o,a,b,c) asm("fma.rn.f32x2 %0, %1, %2, %3;" : "=l"(o) : "l"(a), "l"(b), "l"(c))

// ------------------------------------------------------------------
// Fused kernel: blocks [0,NB) run FPS (serial chain, 1 CTA/cloud),
// blocks [NB, NB+128) run xW = x @ W1[0:64] on the other SMs.
// ------------------------------------------------------------------
__global__ void __launch_bounds__(1024, 1)
fps_xw_kernel(const float* __restrict__ pos, const float* __restrict__ x,
              const float* __restrict__ W1, float* __restrict__ dout, int extras)
{
    extern __shared__ float sm[];
    const int tid = threadIdx.x;

    if (blockIdx.x >= NB) {
        // ------------------ xW GEMM branch ------------------
        float* Wf = sm;                      // 64*128 floats = 32KB
        for (int i = tid; i < 64 * CDIM / 4; i += 1024)
            ((float4*)Wf)[i] = ((const float4*)W1)[i];
        __syncthreads();

        const int warp = tid >> 5, lane = tid & 31;
        const int rbase = (blockIdx.x - NB) * 512 + warp * 16;

        for (int p = 0; p < 8; p++) {
            int r0 = rbase + p * 2, r1 = r0 + 1;
            float2 a = ((const float2*)(x + (size_t)r0 * FDIM))[lane];
            float2 c = ((const float2*)(x + (size_t)r1 * FDIM))[lane];
            float4 a0 = make_float4(0.f, 0.f, 0.f, 0.f);
            float4 a1 = make_float4(0.f, 0.f, 0.f, 0.f);
#pragma unroll
            for (int k2 = 0; k2 < 32; k2++) {
                float xa0 = __shfl_sync(FULLM, a.x, k2);
                float xa1 = __shfl_sync(FULLM, a.y, k2);
                float xc0 = __shfl_sync(FULLM, c.x, k2);
                float xc1 = __shfl_sync(FULLM, c.y, k2);
                float4 w0 = ((float4*)(Wf + (2 * k2) * CDIM))[lane];
                float4 w1 = ((float4*)(Wf + (2 * k2 + 1) * CDIM))[lane];
                a0.x = fmaf(xa0, w0.x, a0.x); a0.y = fmaf(xa0, w0.y, a0.y);
                a0.z = fmaf(xa0, w0.z, a0.z); a0.w = fmaf(xa0, w0.w, a0.w);
                a0.x = fmaf(xa1, w1.x, a0.x); a0.y = fmaf(xa1, w1.y, a0.y);
                a0.z = fmaf(xa1, w1.z, a0.z); a0.w = fmaf(xa1, w1.w, a0.w);
                a1.x = fmaf(xc0, w0.x, a1.x); a1.y = fmaf(xc0, w0.y, a1.y);
                a1.z = fmaf(xc0, w0.z, a1.z); a1.w = fmaf(xc0, w0.w, a1.w);
                a1.x = fmaf(xc1, w1.x, a1.x); a1.y = fmaf(xc1, w1.y, a1.y);
                a1.z = fmaf(xc1, w1.z, a1.z); a1.w = fmaf(xc1, w1.w, a1.w);
            }
            ((float4*)(g_xw + (size_t)r0 * CDIM))[lane] = a0;
            ((float4*)(g_xw + (size_t)r1 * CDIM))[lane] = a1;
        }
        return;
    }

    // ------------------ FPS branch ------------------
    const int b = blockIdx.x;
    const float* pb = pos + (size_t)b * NPB * 3;

    float* sx = sm;
    float* sy = sx + NPB;
    float* sz = sy + NPB;
    unsigned long long* swk = (unsigned long long*)(sz + NPB);   // 2 x 32 parity-buffered slots

    for (int i = tid; i < NPB * 3; i += 1024) {
        float v = pb[i];
        int pt = i / 3, c = i - pt * 3;
        if (c == 0) sx[pt] = v; else if (c == 1) sy[pt] = v; else sz[pt] = v;
    }
    __syncthreads();

    const int warp = tid >> 5, lane = tid & 31;

    // pair p holds point slots tid+2p*1024 (lo) and tid+(2p+1)*1024 (hi)
    unsigned long long pxp[4], pyp[4], pzp[4];
    float dmin[8];
#pragma unroll
    for (int p = 0; p < 4; p++) {
        int i0 = tid + (2 * p) * 1024, i1 = tid + (2 * p + 1) * 1024;
        pxp[p] = pk2(sx[i0], sx[i1]);
        pyp[p] = pk2(sy[i0], sy[i1]);
        pzp[p] = pk2(sz[i0], sz[i1]);
        dmin[2 * p] = 3.4e38f; dmin[2 * p + 1] = 3.4e38f;
    }

    const long long OQ = (long long)NB * MQ * CDIM;
    const long long OB = OQ + (long long)NB * MQ * 3;
    const long long OI = OB + (long long)NB * MQ;

    float qx = sx[0], qy = sy[0], qz = sz[0];
    if (tid == 0) {
        int row = b * MQ;
        g_qpos[row * 3 + 0] = qx; g_qpos[row * 3 + 1] = qy; g_qpos[row * 3 + 2] = qz;
        if (extras) {
            dout[OQ + row * 3 + 0] = qx;
            dout[OQ + row * 3 + 1] = qy;
            dout[OQ + row * 3 + 2] = qz;
            dout[OB + row] = (float)b;
            dout[OI + row] = (float)(b * NPB);
        }
    }

    for (int m = 1; m < MQ; m++) {
        unsigned long long nqx2 = pk2(-qx, -qx);
        unsigned long long nqy2 = pk2(-qy, -qy);
        unsigned long long nqz2 = pk2(-qz, -qz);
#pragma unroll
        for (int p = 0; p < 4; p++) {
            unsigned long long dx, dy, dz, t;
            ADD2(dx, pxp[p], nqx2);
            ADD2(dy, pyp[p], nqy2);
            ADD2(dz, pzp[p], nqz2);
            MUL2(t, dx, dx);
            FMA2(t, dy, dy, t);
            FMA2(t, dz, dz, t);              // ((dx*dx + dy*dy) + dz*dz), per-lane IEEE
            float lo, hi; upk2(lo, hi, t);
            dmin[2 * p]     = fminf(dmin[2 * p],     lo);
            dmin[2 * p + 1] = fminf(dmin[2 * p + 1], hi);
        }

        // value-only max tree (FMNMX on alu pipe, bit-exact)
        float m01 = fmaxf(dmin[0], dmin[1]), m23 = fmaxf(dmin[2], dmin[3]);
        float m45 = fmaxf(dmin[4], dmin[5]), m67 = fmaxf(dmin[6], dmin[7]);
        float bv = fmaxf(fmaxf(m01, m23), fmaxf(m45, m67));

        // warp argmax: REDUX on value, tied lanes contribute (8191 - idx)
        unsigned vb = __float_as_uint(bv);
        unsigned wmax = __reduce_max_sync(FULLM, vb);
        unsigned klo = 0u;
        if (vb == wmax) {
            int bidx = tid;
#pragma unroll
            for (int k = 7; k >= 0; k--)
                if (__float_as_uint(dmin[k]) == wmax) bidx = tid + k * 1024;
            klo = (unsigned)(8191 - bidx);   // max(klo) == min global index
        }
        klo = __reduce_max_sync(FULLM, klo);
        if (lane == 0)
            swk[((m & 1) << 5) + warp] = ((unsigned long long)wmax << 32) | klo;
        __syncthreads();                     // drains the 32 STS.64

        // block argmax: every warp reduces the 32 fresh slots (no atomics)
        unsigned long long wv = swk[((m & 1) << 5) + lane];
        unsigned hi = (unsigned)(wv >> 32), lo = (unsigned)wv;
        unsigned gm = __reduce_max_sync(FULLM, hi);
        unsigned cand = (hi == gm) ? lo : 0u;
        unsigned blklo = __reduce_max_sync(FULLM, cand);
        int win = 8191 - (int)blklo;

        qx = sx[win]; qy = sy[win]; qz = sz[win];

        if (tid == 0) {
            int row = b * MQ + m;
            g_qpos[row * 3 + 0] = qx; g_qpos[row * 3 + 1] = qy; g_qpos[row * 3 + 2] = qz;
            if (extras) {
                dout[OQ + row * 3 + 0] = qx;
                dout[OQ + row * 3 + 1] = qy;
                dout[OQ + row * 3 + 2] = qz;
                dout[OB + row] = (float)b;
                dout[OI + row] = (float)(b * NPB + win);
            }
        }
    }
}

// ------------------------------------------------------------------
// Ball query (exact top-K set) + fused pos-MLP + max + relu
// grid 128 (16 CTAs/cloud), 1024 threads (32 warps); each warp: 4 queries
// ------------------------------------------------------------------
__global__ void __launch_bounds__(1024)
ballconv_kernel(const float* __restrict__ pos, const float* __restrict__ W1,
                const float* __restrict__ b1, float* __restrict__ dout)
{
    extern __shared__ float smem[];
    float* spx = smem;
    float* spy = spx + NPB;
    float* spz = spy + NPB;
    unsigned long long* skey = (unsigned long long*)(spz + NPB);   // 32 warps * CAP
    int* ssel = (int*)(skey + 32 * CAP);                           // 32 warps * KNN

    const int b   = blockIdx.x >> 4;
    const int sub = blockIdx.x & 15;
    const int tid = threadIdx.x, warp = tid >> 5, lane = tid & 31;
    const float* pb = pos + (size_t)b * NPB * 3;

    for (int i = tid; i < NPB * 3; i += 1024) {
        float v = pb[i];
        int pt = i / 3, c = i - pt * 3;
        if (c == 0) spx[pt] = v; else if (c == 1) spy[pt] = v; else spz[pt] = v;
    }

    float4 wp0 = *(const float4*)(W1 + 64 * CDIM + 4 * lane);
    float4 wp1 = *(const float4*)(W1 + 65 * CDIM + 4 * lane);
    float4 wp2 = *(const float4*)(W1 + 66 * CDIM + 4 * lane);
    float4 bb  = *(const float4*)(b1 + 4 * lane);
    __syncthreads();

    unsigned long long* mykey = skey + warp * CAP;
    int* mysel = ssel + warp * KNN;
    const unsigned ltmask = (1u << lane) - 1u;
    const int qbase = sub * 128 + warp * 4;

    for (int qi = 0; qi < 4; qi++) {
        int m = qbase + qi;
        int row = b * MQ + m;
        float qx = g_qpos[row * 3 + 0];
        float qy = g_qpos[row * 3 + 1];
        float qz = g_qpos[row * 3 + 2];
        unsigned long long nqx2 = pk2(-qx, -qx);
        unsigned long long nqy2 = pk2(-qy, -qy);
        unsigned long long nqz2 = pk2(-qz, -qz);

        // packed scan: 2 points per lane per iter (same IEEE contraction as ref)
        int cnt = 0;
        for (int t = 0; t < NPB / 64; t++) {
            int i0 = t * 64 + lane, i1 = i0 + 32;
            unsigned long long ppx = pk2(spx[i0], spx[i1]);
            unsigned long long ppy = pk2(spy[i0], spy[i1]);
            unsigned long long ppz = pk2(spz[i0], spz[i1]);
            unsigned long long dx, dy, dz, d2p;
            ADD2(dx, ppx, nqx2);
            ADD2(dy, ppy, nqy2);
            ADD2(dz, ppz, nqz2);
            MUL2(d2p, dx, dx);
            FMA2(d2p, dy, dy, d2p);
            FMA2(d2p, dz, dz, d2p);
            float d2a, d2b; upk2(d2a, d2b, d2p);
            bool in0 = (d2a <= R2C), in1 = (d2b <= R2C);
            unsigned mk0 = __ballot_sync(FULLM, in0);
            unsigned mk1 = __ballot_sync(FULLM, in1);
            if (in0) {
                int off = cnt + __popc(mk0 & ltmask);
                if (off < CAP)
                    mykey[off] = ((unsigned long long)__float_as_uint(d2a) << 32) | (unsigned)i0;
            }
            cnt += __popc(mk0);
            if (in1) {
                int off = cnt + __popc(mk1 & ltmask);
                if (off < CAP)
                    mykey[off] = ((unsigned long long)__float_as_uint(d2b) << 32) | (unsigned)i1;
            }
            cnt += __popc(mk1);
        }
        if (cnt > CAP) cnt = CAP;

        int nsel;
        if (cnt <= KNN) {
            nsel = cnt;
            if (lane < cnt) mysel[lane] = (int)(mykey[lane] & 0xffffffffull);
        } else {
            nsel = KNN;
            int written = 0;
            for (int base = 0; base < cnt; base += 32) {
                int c = base + lane;
                bool s = false;
                unsigned long long ka = 0ull;
                if (c < cnt) {
                    ka = mykey[c];
                    int rank = 0;
                    for (int e = 0; e < cnt; e++) rank += (mykey[e] < ka) ? 1 : 0;
                    s = (rank < KNN);
                }
                unsigned mk = __ballot_sync(FULLM, s);
                if (s) mysel[written + __popc(mk & ltmask)] = (int)(ka & 0xffffffffull);
                written += __popc(mk);
            }
        }
        __syncwarp();

        float4 vm = make_float4(-3.4e38f, -3.4e38f, -3.4e38f, -3.4e38f);
        for (int s = 0; s < nsel; s++) {
            int j = mysel[s];
            float dx = spx[j] - qx, dy = spy[j] - qy, dz = spz[j] - qz;
            float4 xw = *(const float4*)(g_xw + (size_t)(b * NPB + j) * CDIM + 4 * lane);
            float v0 = fmaf(dz, wp2.x, fmaf(dy, wp1.x, fmaf(dx, wp0.x, xw.x)));
            float v1 = fmaf(dz, wp2.y, fmaf(dy, wp1.y, fmaf(dx, wp0.y, xw.y)));
            float v2 = fmaf(dz, wp2.z, fmaf(dy, wp1.z, fmaf(dx, wp0.z, xw.z)));
            float v3 = fmaf(dz, wp2.w, fmaf(dy, wp1.w, fmaf(dx, wp0.w, xw.w)));
            vm.x = fmaxf(vm.x, v0); vm.y = fmaxf(vm.y, v1);
            vm.z = fmaxf(vm.z, v2); vm.w = fmaxf(vm.w, v3);
        }
        float4 o;
        o.x = fmaxf(vm.x + bb.x, 0.0f);
        o.y = fmaxf(vm.y + bb.y, 0.0f);
        o.z = fmaxf(vm.z + bb.z, 0.0f);
        o.w = fmaxf(vm.w + bb.w, 0.0f);
        *(float4*)(dout + (size_t)row * CDIM + 4 * lane) = o;
        __syncwarp();
    }
}

// ------------------------------------------------------------------
extern "C" void kernel_launch(void* const* d_in, const int* in_sizes, int n_in,
                              void* d_out, int out_size)
{
    const float *x = nullptr, *pos = nullptr, *W1 = nullptr, *b1 = nullptr;
    for (int i = 0; i < n_in; i++) {
        switch (in_sizes[i]) {
            case NROWS * FDIM:      x   = (const float*)d_in[i]; break;
            case NROWS * 3:         pos = (const float*)d_in[i]; break;
            case (FDIM + 3) * CDIM: W1  = (const float*)d_in[i]; break;
            case CDIM:              b1  = (const float*)d_in[i]; break;
            default: break;                                        // batch (unused)
        }
    }
    float* out = (float*)d_out;
    long long total = (long long)NB * MQ * CDIM + (long long)NB * MQ * 3 + 2ll * NB * MQ;
    int extras = ((long long)out_size >= total) ? 1 : 0;

    size_t smem1 = (size_t)3 * NPB * 4 + 64 * 8;                   // positions + 2x32 u64 slots
    cudaFuncSetAttribute(fps_xw_kernel, cudaFuncAttributeMaxDynamicSharedMemorySize, (int)smem1);
    fps_xw_kernel<<<NB + 128, 1024, smem1>>>(pos, x, W1, out, extras);

    // 96KB positions + 64KB candidate keys (32 warps) + 4KB sel
    size_t smem2 = (size_t)3 * NPB * 4 + (size_t)32 * CAP * 8 + (size_t)32 * KNN * 4; // 167936
    cudaFuncSetAttribute(ballconv_kernel, cudaFuncAttributeMaxDynamicSharedMemorySize, (int)smem2);
    ballconv_kernel<<<128, 1024, smem2>>>(pos, W1, b1, out);
}

// round 14
// speedup vs baseline: 1.3758x; 1.1175x over previous
#include <cuda_runtime.h>
#include <cstdint>

#define NB    8
#define NPB   8192
#define FDIM  64
#define MQ    2048
#define KNN   32
#define CDIM  128
#define R2C   0.01f
#define NROWS (NB*NPB)
#define CAP   256
#define FULLM 0xffffffffu
#define FPST  512                       // threads in fused kernel
#define PPT   16                        // points per FPS thread

// scratch (device globals — no allocation allowed)
__device__ float g_xw[(size_t)NROWS * CDIM];   // x @ W1[0:64]
__device__ float g_qpos[NB * MQ * 3];

// ---- packed f32x2 helpers (sm_103a; only add/mul/fma exist packed) ----
__device__ __forceinline__ unsigned long long pk2(float lo, float hi) {
    unsigned long long r;
    asm("mov.b64 %0, {%1,%2};" : "=l"(r) : "f"(lo), "f"(hi));
    return r;
}
__device__ __forceinline__ void upk2(float& lo, float& hi, unsigned long long v) {
    asm("mov.b64 {%0,%1}, %2;" : "=f"(lo), "=f"(hi) : "l"(v));
}
#define ADD2(o,a,b)   asm("add.rn.f32x2 %0, %1, %2;"     : "=l"(o) : "l"(a), "l"(b))
#define MUL2(o,a,b)   asm("mul.rn.f32x2 %0, %1, %2;"     : "=l"(o) : "l"(a), "l"(b))
#define FMA2(o,a,b,c) asm("fma.rn.f32x2 %0, %1, %2, %3;" : "=l"(o) : "l"(a), "l"(b), "l"(c))

// ------------------------------------------------------------------
// Fused kernel (512 threads): blocks [0,NB) run FPS (1 CTA/cloud),
// blocks [NB, NB+128) run xW = x @ W1[0:64] on the other SMs.
// ------------------------------------------------------------------
__global__ void __launch_bounds__(FPST, 1)
fps_xw_kernel(const float* __restrict__ pos, const float* __restrict__ x,
              const float* __restrict__ W1, float* __restrict__ dout, int extras)
{
    extern __shared__ float sm[];
    const int tid = threadIdx.x;
    const int warp = tid >> 5, lane = tid & 31;

    if (blockIdx.x >= NB) {
        // ------------------ xW GEMM branch (16 warps x 32 rows) ------------------
        float* Wf = sm;                      // 64*128 floats = 32KB
        for (int i = tid; i < 64 * CDIM / 4; i += FPST)
            ((float4*)Wf)[i] = ((const float4*)W1)[i];
        __syncthreads();

        const int rbase = (blockIdx.x - NB) * 512 + warp * 32;

        for (int p = 0; p < 16; p++) {
            int r0 = rbase + p * 2, r1 = r0 + 1;
            float2 a = ((const float2*)(x + (size_t)r0 * FDIM))[lane];
            float2 c = ((const float2*)(x + (size_t)r1 * FDIM))[lane];
            float4 a0 = make_float4(0.f, 0.f, 0.f, 0.f);
            float4 a1 = make_float4(0.f, 0.f, 0.f, 0.f);
#pragma unroll
            for (int k2 = 0; k2 < 32; k2++) {
                float xa0 = __shfl_sync(FULLM, a.x, k2);
                float xa1 = __shfl_sync(FULLM, a.y, k2);
                float xc0 = __shfl_sync(FULLM, c.x, k2);
                float xc1 = __shfl_sync(FULLM, c.y, k2);
                float4 w0 = ((float4*)(Wf + (2 * k2) * CDIM))[lane];
                float4 w1 = ((float4*)(Wf + (2 * k2 + 1) * CDIM))[lane];
                a0.x = fmaf(xa0, w0.x, a0.x); a0.y = fmaf(xa0, w0.y, a0.y);
                a0.z = fmaf(xa0, w0.z, a0.z); a0.w = fmaf(xa0, w0.w, a0.w);
                a0.x = fmaf(xa1, w1.x, a0.x); a0.y = fmaf(xa1, w1.y, a0.y);
                a0.z = fmaf(xa1, w1.z, a0.z); a0.w = fmaf(xa1, w1.w, a0.w);
                a1.x = fmaf(xc0, w0.x, a1.x); a1.y = fmaf(xc0, w0.y, a1.y);
                a1.z = fmaf(xc0, w0.z, a1.z); a1.w = fmaf(xc0, w0.w, a1.w);
                a1.x = fmaf(xc1, w1.x, a1.x); a1.y = fmaf(xc1, w1.y, a1.y);
                a1.z = fmaf(xc1, w1.z, a1.z); a1.w = fmaf(xc1, w1.w, a1.w);
            }
            ((float4*)(g_xw + (size_t)r0 * CDIM))[lane] = a0;
            ((float4*)(g_xw + (size_t)r1 * CDIM))[lane] = a1;
        }
        return;
    }

    // ------------------ FPS branch (16 warps x 16 points/thread) ------------------
    const int b = blockIdx.x;
    const float* pb = pos + (size_t)b * NPB * 3;

    float* sx = sm;
    float* sy = sx + NPB;
    float* sz = sy + NPB;
    unsigned long long* swk = (unsigned long long*)(sz + NPB);   // 2 x 16 parity slots

    for (int i = tid; i < NPB * 3; i += FPST) {
        float v = pb[i];
        int pt = i / 3, c = i - pt * 3;
        if (c == 0) sx[pt] = v; else if (c == 1) sy[pt] = v; else sz[pt] = v;
    }
    __syncthreads();

    // pair p holds point slots tid+2p*512 (lo) and tid+(2p+1)*512 (hi)
    unsigned long long pxp[PPT / 2], pyp[PPT / 2], pzp[PPT / 2];
    float dmin[PPT];
#pragma unroll
    for (int p = 0; p < PPT / 2; p++) {
        int i0 = tid + (2 * p) * FPST, i1 = tid + (2 * p + 1) * FPST;
        pxp[p] = pk2(sx[i0], sx[i1]);
        pyp[p] = pk2(sy[i0], sy[i1]);
        pzp[p] = pk2(sz[i0], sz[i1]);
        dmin[2 * p] = 3.4e38f; dmin[2 * p + 1] = 3.4e38f;
    }

    const long long OQ = (long long)NB * MQ * CDIM;
    const long long OB = OQ + (long long)NB * MQ * 3;
    const long long OI = OB + (long long)NB * MQ;

    float qx = sx[0], qy = sy[0], qz = sz[0];
    if (tid == 0) {
        int row = b * MQ;
        g_qpos[row * 3 + 0] = qx; g_qpos[row * 3 + 1] = qy; g_qpos[row * 3 + 2] = qz;
        if (extras) {
            dout[OQ + row * 3 + 0] = qx;
            dout[OQ + row * 3 + 1] = qy;
            dout[OQ + row * 3 + 2] = qz;
            dout[OB + row] = (float)b;
            dout[OI + row] = (float)(b * NPB);
        }
    }

    for (int m = 1; m < MQ; m++) {
        unsigned long long nqx2 = pk2(-qx, -qx);
        unsigned long long nqy2 = pk2(-qy, -qy);
        unsigned long long nqz2 = pk2(-qz, -qz);
#pragma unroll
        for (int p = 0; p < PPT / 2; p++) {
            unsigned long long dx, dy, dz, t;
            ADD2(dx, pxp[p], nqx2);
            ADD2(dy, pyp[p], nqy2);
            ADD2(dz, pzp[p], nqz2);
            MUL2(t, dx, dx);
            FMA2(t, dy, dy, t);
            FMA2(t, dz, dz, t);              // ((dx*dx + dy*dy) + dz*dz), per-lane IEEE
            float lo, hi; upk2(lo, hi, t);
            dmin[2 * p]     = fminf(dmin[2 * p],     lo);
            dmin[2 * p + 1] = fminf(dmin[2 * p + 1], hi);
        }

        // value-only max tree (FMNMX, bit-exact)
        float t0 = fmaxf(fmaxf(dmin[0], dmin[1]),  fmaxf(dmin[2], dmin[3]));
        float t1 = fmaxf(fmaxf(dmin[4], dmin[5]),  fmaxf(dmin[6], dmin[7]));
        float t2 = fmaxf(fmaxf(dmin[8], dmin[9]),  fmaxf(dmin[10], dmin[11]));
        float t3 = fmaxf(fmaxf(dmin[12], dmin[13]), fmaxf(dmin[14], dmin[15]));
        float bv = fmaxf(fmaxf(t0, t1), fmaxf(t2, t3));

        // warp argmax: REDUX on value, tied lanes contribute (8191 - idx)
        unsigned vb = __float_as_uint(bv);
        unsigned wmax = __reduce_max_sync(FULLM, vb);
        unsigned klo = 0u;
        if (vb == wmax) {
            int bidx = tid;
#pragma unroll
            for (int k = PPT - 1; k >= 0; k--)
                if (__float_as_uint(dmin[k]) == wmax) bidx = tid + k * FPST;
            klo = (unsigned)(8191 - bidx);   // max(klo) == min global index
        }
        klo = __reduce_max_sync(FULLM, klo);
        if (lane == 0)
            swk[((m & 1) << 4) + warp] = ((unsigned long long)wmax << 32) | klo;
        __syncthreads();                     // drains the 16 STS.64

        // block argmax: every warp reduces the 16 fresh slots (duplicated reads OK)
        unsigned long long wv = swk[((m & 1) << 4) + (lane & 15)];
        unsigned hi = (unsigned)(wv >> 32), lo = (unsigned)wv;
        unsigned gm = __reduce_max_sync(FULLM, hi);
        unsigned cand = (hi == gm) ? lo : 0u;
        unsigned blklo = __reduce_max_sync(FULLM, cand);
        int win = 8191 - (int)blklo;

        qx = sx[win]; qy = sy[win]; qz = sz[win];

        if (tid == 0) {
            int row = b * MQ + m;
            g_qpos[row * 3 + 0] = qx; g_qpos[row * 3 + 1] = qy; g_qpos[row * 3 + 2] = qz;
            if (extras) {
                dout[OQ + row * 3 + 0] = qx;
                dout[OQ + row * 3 + 1] = qy;
                dout[OQ + row * 3 + 2] = qz;
                dout[OB + row] = (float)b;
                dout[OI + row] = (float)(b * NPB + win);
            }
        }
    }
}

// ------------------------------------------------------------------
// Ball query (exact top-K set) + fused pos-MLP + max + relu
// grid 128 (16 CTAs/cloud), 1024 threads (32 warps); each warp: 4 queries
// ------------------------------------------------------------------
__global__ void __launch_bounds__(1024)
ballconv_kernel(const float* __restrict__ pos, const float* __restrict__ W1,
                const float* __restrict__ b1, float* __restrict__ dout)
{
    extern __shared__ float smem[];
    float* spx = smem;
    float* spy = spx + NPB;
    float* spz = spy + NPB;
    unsigned long long* skey = (unsigned long long*)(spz + NPB);   // 32 warps * CAP
    int* ssel = (int*)(skey + 32 * CAP);                           // 32 warps * KNN

    const int b   = blockIdx.x >> 4;
    const int sub = blockIdx.x & 15;
    const int tid = threadIdx.x, warp = tid >> 5, lane = tid & 31;
    const float* pb = pos + (size_t)b * NPB * 3;

    for (int i = tid; i < NPB * 3; i += 1024) {
        float v = pb[i];
        int pt = i / 3, c = i - pt * 3;
        if (c == 0) spx[pt] = v; else if (c == 1) spy[pt] = v; else spz[pt] = v;
    }

    float4 wp0 = *(const float4*)(W1 + 64 * CDIM + 4 * lane);
    float4 wp1 = *(const float4*)(W1 + 65 * CDIM + 4 * lane);
    float4 wp2 = *(const float4*)(W1 + 66 * CDIM + 4 * lane);
    float4 bb  = *(const float4*)(b1 + 4 * lane);
    __syncthreads();

    unsigned long long* mykey = skey + warp * CAP;
    int* mysel = ssel + warp * KNN;
    const unsigned ltmask = (1u << lane) - 1u;
    const int qbase = sub * 128 + warp * 4;

    for (int qi = 0; qi < 4; qi++) {
        int m = qbase + qi;
        int row = b * MQ + m;
        float qx = g_qpos[row * 3 + 0];
        float qy = g_qpos[row * 3 + 1];
        float qz = g_qpos[row * 3 + 2];
        unsigned long long nqx2 = pk2(-qx, -qx);
        unsigned long long nqy2 = pk2(-qy, -qy);
        unsigned long long nqz2 = pk2(-qz, -qz);

        // packed scan: 2 points per lane per iter (same IEEE contraction as ref)
        int cnt = 0;
        for (int t = 0; t < NPB / 64; t++) {
            int i0 = t * 64 + lane, i1 = i0 + 32;
            unsigned long long ppx = pk2(spx[i0], spx[i1]);
            unsigned long long ppy = pk2(spy[i0], spy[i1]);
            unsigned long long ppz = pk2(spz[i0], spz[i1]);
            unsigned long long dx, dy, dz, d2p;
            ADD2(dx, ppx, nqx2);
            ADD2(dy, ppy, nqy2);
            ADD2(dz, ppz, nqz2);
            MUL2(d2p, dx, dx);
            FMA2(d2p, dy, dy, d2p);
            FMA2(d2p, dz, dz, d2p);
            float d2a, d2b; upk2(d2a, d2b, d2p);
            bool in0 = (d2a <= R2C), in1 = (d2b <= R2C);
            unsigned mk0 = __ballot_sync(FULLM, in0);
            unsigned mk1 = __ballot_sync(FULLM, in1);
            if (in0) {
                int off = cnt + __popc(mk0 & ltmask);
                if (off < CAP)
                    mykey[off] = ((unsigned long long)__float_as_uint(d2a) << 32) | (unsigned)i0;
            }
            cnt += __popc(mk0);
            if (in1) {
                int off = cnt + __popc(mk1 & ltmask);
                if (off < CAP)
                    mykey[off] = ((unsigned long long)__float_as_uint(d2b) << 32) | (unsigned)i1;
            }
            cnt += __popc(mk1);
        }
        if (cnt > CAP) cnt = CAP;

        int nsel;
        if (cnt <= KNN) {
            nsel = cnt;
            if (lane < cnt) mysel[lane] = (int)(mykey[lane] & 0xffffffffull);
        } else {
            nsel = KNN;
            int written = 0;
            for (int base = 0; base < cnt; base += 32) {
                int c = base + lane;
                bool s = false;
                unsigned long long ka = 0ull;
                if (c < cnt) {
                    ka = mykey[c];
                    int rank = 0;
                    for (int e = 0; e < cnt; e++) rank += (mykey[e] < ka) ? 1 : 0;
                    s = (rank < KNN);
                }
                unsigned mk = __ballot_sync(FULLM, s);
                if (s) mysel[written + __popc(mk & ltmask)] = (int)(ka & 0xffffffffull);
                written += __popc(mk);
            }
        }
        __syncwarp();

        float4 vm = make_float4(-3.4e38f, -3.4e38f, -3.4e38f, -3.4e38f);
        for (int s = 0; s < nsel; s++) {
            int j = mysel[s];
            float dx = spx[j] - qx, dy = spy[j] - qy, dz = spz[j] - qz;
            float4 xw = *(const float4*)(g_xw + (size_t)(b * NPB + j) * CDIM + 4 * lane);
            float v0 = fmaf(dz, wp2.x, fmaf(dy, wp1.x, fmaf(dx, wp0.x, xw.x)));
            float v1 = fmaf(dz, wp2.y, fmaf(dy, wp1.y, fmaf(dx, wp0.y, xw.y)));
            float v2 = fmaf(dz, wp2.z, fmaf(dy, wp1.z, fmaf(dx, wp0.z, xw.z)));
            float v3 = fmaf(dz, wp2.w, fmaf(dy, wp1.w, fmaf(dx, wp0.w, xw.w)));
            vm.x = fmaxf(vm.x, v0); vm.y = fmaxf(vm.y, v1);
            vm.z = fmaxf(vm.z, v2); vm.w = fmaxf(vm.w, v3);
        }
        float4 o;
        o.x = fmaxf(vm.x + bb.x, 0.0f);
        o.y = fmaxf(vm.y + bb.y, 0.0f);
        o.z = fmaxf(vm.z + bb.z, 0.0f);
        o.w = fmaxf(vm.w + bb.w, 0.0f);
        *(float4*)(dout + (size_t)row * CDIM + 4 * lane) = o;
        __syncwarp();
    }
}

// ------------------------------------------------------------------
extern "C" void kernel_launch(void* const* d_in, const int* in_sizes, int n_in,
                              void* d_out, int out_size)
{
    const float *x = nullptr, *pos = nullptr, *W1 = nullptr, *b1 = nullptr;
    for (int i = 0; i < n_in; i++) {
        switch (in_sizes[i]) {
            case NROWS * FDIM:      x   = (const float*)d_in[i]; break;
            case NROWS * 3:         pos = (const float*)d_in[i]; break;
            case (FDIM + 3) * CDIM: W1  = (const float*)d_in[i]; break;
            case CDIM:              b1  = (const float*)d_in[i]; break;
            default: break;                                        // batch (unused)
        }
    }
    float* out = (float*)d_out;
    long long total = (long long)NB * MQ * CDIM + (long long)NB * MQ * 3 + 2ll * NB * MQ;
    int extras = ((long long)out_size >= total) ? 1 : 0;

    size_t smem1 = (size_t)3 * NPB * 4 + 32 * 8;                   // positions + 2x16 u64 slots
    cudaFuncSetAttribute(fps_xw_kernel, cudaFuncAttributeMaxDynamicSharedMemorySize, (int)smem1);
    fps_xw_kernel<<<NB + 128, FPST, smem1>>>(pos, x, W1, out, extras);

    // 96KB positions + 64KB candidate keys (32 warps) + 4KB sel
    size_t smem2 = (size_t)3 * NPB * 4 + (size_t)32 * CAP * 8 + (size_t)32 * KNN * 4; // 167936
    cudaFuncSetAttribute(ballconv_kernel, cudaFuncAttributeMaxDynamicSharedMemorySize, (int)smem2);
    ballconv_kernel<<<128, 1024, smem2>>>(pos, W1, b1, out);
}

// round 16
// speedup vs baseline: 1.4062x; 1.0221x over previous
#include <cuda_runtime.h>
#include <cstdint>

#define NB    8
#define NPB   8192
#define FDIM  64
#define MQ    2048
#define KNN   32
#define CDIM  128
#define R2C   0.01f
#define NROWS (NB*NPB)
#define CAP   256
#define FULLM 0xffffffffu
#define FPST  256                       // threads in fused kernel
#define NWARP (FPST/32)                 // 8 warps
#define PPT   32                        // points per FPS thread

// scratch (device globals — no allocation allowed)
__device__ float g_xw[(size_t)NROWS * CDIM];   // x @ W1[0:64]
__device__ float g_qpos[NB * MQ * 3];

// ---- packed f32x2 helpers (sm_103a; only add/mul/fma exist packed) ----
__device__ __forceinline__ unsigned long long pk2(float lo, float hi) {
    unsigned long long r;
    asm("mov.b64 %0, {%1,%2};" : "=l"(r) : "f"(lo), "f"(hi));
    return r;
}
__device__ __forceinline__ void upk2(float& lo, float& hi, unsigned long long v) {
    asm("mov.b64 {%0,%1}, %2;" : "=f"(lo), "=f"(hi) : "l"(v));
}
#define ADD2(o,a,b)   asm("add.rn.f32x2 %0, %1, %2;"     : "=l"(o) : "l"(a), "l"(b))
#define MUL2(o,a,b)   asm("mul.rn.f32x2 %0, %1, %2;"     : "=l"(o) : "l"(a), "l"(b))
#define FMA2(o,a,b,c) asm("fma.rn.f32x2 %0, %1, %2, %3;" : "=l"(o) : "l"(a), "l"(b), "l"(c))

// ------------------------------------------------------------------
// Fused kernel (256 threads): blocks [0,NB) run FPS (1 CTA/cloud),
// blocks [NB, NB+128) run xW = x @ W1[0:64] on the other SMs.
// ------------------------------------------------------------------
__global__ void __launch_bounds__(FPST, 1)
fps_xw_kernel(const float* __restrict__ pos, const float* __restrict__ x,
              const float* __restrict__ W1, float* __restrict__ dout, int extras)
{
    extern __shared__ float sm[];
    const int tid = threadIdx.x;
    const int warp = tid >> 5, lane = tid & 31;

    if (blockIdx.x >= NB) {
        // ------------------ xW GEMM branch (8 warps x 64 rows) ------------------
        float* Wf = sm;                      // 64*128 floats = 32KB
        for (int i = tid; i < 64 * CDIM / 4; i += FPST)
            ((float4*)Wf)[i] = ((const float4*)W1)[i];
        __syncthreads();

        const int rbase = (blockIdx.x - NB) * 512 + warp * 64;

        for (int p = 0; p < 32; p++) {
            int r0 = rbase + p * 2, r1 = r0 + 1;
            float2 a = ((const float2*)(x + (size_t)r0 * FDIM))[lane];
            float2 c = ((const float2*)(x + (size_t)r1 * FDIM))[lane];
            float4 a0 = make_float4(0.f, 0.f, 0.f, 0.f);
            float4 a1 = make_float4(0.f, 0.f, 0.f, 0.f);
#pragma unroll
            for (int k2 = 0; k2 < 32; k2++) {
                float xa0 = __shfl_sync(FULLM, a.x, k2);
                float xa1 = __shfl_sync(FULLM, a.y, k2);
                float xc0 = __shfl_sync(FULLM, c.x, k2);
                float xc1 = __shfl_sync(FULLM, c.y, k2);
                float4 w0 = ((float4*)(Wf + (2 * k2) * CDIM))[lane];
                float4 w1 = ((float4*)(Wf + (2 * k2 + 1) * CDIM))[lane];
                a0.x = fmaf(xa0, w0.x, a0.x); a0.y = fmaf(xa0, w0.y, a0.y);
                a0.z = fmaf(xa0, w0.z, a0.z); a0.w = fmaf(xa0, w0.w, a0.w);
                a0.x = fmaf(xa1, w1.x, a0.x); a0.y = fmaf(xa1, w1.y, a0.y);
                a0.z = fmaf(xa1, w1.z, a0.z); a0.w = fmaf(xa1, w1.w, a0.w);
                a1.x = fmaf(xc0, w0.x, a1.x); a1.y = fmaf(xc0, w0.y, a1.y);
                a1.z = fmaf(xc0, w0.z, a1.z); a1.w = fmaf(xc0, w0.w, a1.w);
                a1.x = fmaf(xc1, w1.x, a1.x); a1.y = fmaf(xc1, w1.y, a1.y);
                a1.z = fmaf(xc1, w1.z, a1.z); a1.w = fmaf(xc1, w1.w, a1.w);
            }
            ((float4*)(g_xw + (size_t)r0 * CDIM))[lane] = a0;
            ((float4*)(g_xw + (size_t)r1 * CDIM))[lane] = a1;
        }
        return;
    }

    // ------------------ FPS branch (8 warps x 32 points/thread) ------------------
    const int b = blockIdx.x;
    const float* pb = pos + (size_t)b * NPB * 3;

    float* sx = sm;
    float* sy = sx + NPB;
    float* sz = sy + NPB;
    unsigned long long* swk = (unsigned long long*)(sz + NPB);   // 2 x 8 parity slots

    for (int i = tid; i < NPB * 3; i += FPST) {
        float v = pb[i];
        int pt = i / 3, c = i - pt * 3;
        if (c == 0) sx[pt] = v; else if (c == 1) sy[pt] = v; else sz[pt] = v;
    }
    __syncthreads();

    // pair p holds point slots tid+2p*256 (lo) and tid+(2p+1)*256 (hi)
    unsigned long long pxp[PPT / 2], pyp[PPT / 2], pzp[PPT / 2];
    float dmin[PPT];
#pragma unroll
    for (int p = 0; p < PPT / 2; p++) {
        int i0 = tid + (2 * p) * FPST, i1 = tid + (2 * p + 1) * FPST;
        pxp[p] = pk2(sx[i0], sx[i1]);
        pyp[p] = pk2(sy[i0], sy[i1]);
        pzp[p] = pk2(sz[i0], sz[i1]);
        dmin[2 * p] = 3.4e38f; dmin[2 * p + 1] = 3.4e38f;
    }

    const long long OQ = (long long)NB * MQ * CDIM;
    const long long OB = OQ + (long long)NB * MQ * 3;
    const long long OI = OB + (long long)NB * MQ;

    float qx = sx[0], qy = sy[0], qz = sz[0];
    if (tid == 0) {
        int row = b * MQ;
        g_qpos[row * 3 + 0] = qx; g_qpos[row * 3 + 1] = qy; g_qpos[row * 3 + 2] = qz;
        if (extras) {
            dout[OQ + row * 3 + 0] = qx;
            dout[OQ + row * 3 + 1] = qy;
            dout[OQ + row * 3 + 2] = qz;
            dout[OB + row] = (float)b;
            dout[OI + row] = (float)(b * NPB);
        }
    }

    for (int m = 1; m < MQ; m++) {
        unsigned long long nqx2 = pk2(-qx, -qx);
        unsigned long long nqy2 = pk2(-qy, -qy);
        unsigned long long nqz2 = pk2(-qz, -qz);
#pragma unroll
        for (int p = 0; p < PPT / 2; p++) {
            unsigned long long dx, dy, dz, t;
            ADD2(dx, pxp[p], nqx2);
            ADD2(dy, pyp[p], nqy2);
            ADD2(dz, pzp[p], nqz2);
            MUL2(t, dx, dx);
            FMA2(t, dy, dy, t);
            FMA2(t, dz, dz, t);              // ((dx*dx + dy*dy) + dz*dz), per-lane IEEE
            float lo, hi; upk2(lo, hi, t);
            dmin[2 * p]     = fminf(dmin[2 * p],     lo);
            dmin[2 * p + 1] = fminf(dmin[2 * p + 1], hi);
        }

        // value-only binary max tree into temps (dmin must persist)
        float red[PPT / 2];
#pragma unroll
        for (int k = 0; k < PPT / 2; k++)
            red[k] = fmaxf(dmin[k], dmin[k + PPT / 2]);
#pragma unroll
        for (int s = PPT / 4; s >= 1; s >>= 1)
#pragma unroll
            for (int k = 0; k < s; k++)
                red[k] = fmaxf(red[k], red[k + s]);
        float bv = red[0];

        // warp argmax: REDUX on value, tied lanes contribute (8191 - idx)
        unsigned vb = __float_as_uint(bv);
        unsigned wmax = __reduce_max_sync(FULLM, vb);
        unsigned klo = 0u;
        if (vb == wmax) {
            int bidx = tid;
#pragma unroll
            for (int k = PPT - 1; k >= 0; k--)
                if (__float_as_uint(dmin[k]) == wmax) bidx = tid + k * FPST;
            klo = (unsigned)(8191 - bidx);   // max(klo) == min global index
        }
        klo = __reduce_max_sync(FULLM, klo);
        if (lane == 0)
            swk[((m & 1) << 3) + warp] = ((unsigned long long)wmax << 32) | klo;
        __syncthreads();                     // drains the 8 STS.64

        // block argmax: every warp reduces the 8 fresh slots (duplicated reads OK)
        unsigned long long wv = swk[((m & 1) << 3) + (lane & 7)];
        unsigned hi = (unsigned)(wv >> 32), lo = (unsigned)wv;
        unsigned gm = __reduce_max_sync(FULLM, hi);
        unsigned cand = (hi == gm) ? lo : 0u;
        unsigned blklo = __reduce_max_sync(FULLM, cand);
        int win = 8191 - (int)blklo;

        qx = sx[win]; qy = sy[win]; qz = sz[win];

        if (tid == 0) {
            int row = b * MQ + m;
            g_qpos[row * 3 + 0] = qx; g_qpos[row * 3 + 1] = qy; g_qpos[row * 3 + 2] = qz;
            if (extras) {
                dout[OQ + row * 3 + 0] = qx;
                dout[OQ + row * 3 + 1] = qy;
                dout[OQ + row * 3 + 2] = qz;
                dout[OB + row] = (float)b;
                dout[OI + row] = (float)(b * NPB + win);
            }
        }
    }
}

// ------------------------------------------------------------------
// Ball query (exact top-K set) + fused pos-MLP + max + relu
// grid 128 (16 CTAs/cloud), 1024 threads (32 warps); each warp: 4 queries
// ------------------------------------------------------------------
__global__ void __launch_bounds__(1024)
ballconv_kernel(const float* __restrict__ pos, const float* __restrict__ W1,
                const float* __restrict__ b1, float* __restrict__ dout)
{
    extern __shared__ float smem[];
    float* spx = smem;
    float* spy = spx + NPB;
    float* spz = spy + NPB;
    unsigned long long* skey = (unsigned long long*)(spz + NPB);   // 32 warps * CAP
    int* ssel = (int*)(skey + 32 * CAP);                           // 32 warps * KNN

    const int b   = blockIdx.x >> 4;
    const int sub = blockIdx.x & 15;
    const int tid = threadIdx.x, warp = tid >> 5, lane = tid & 31;
    const float* pb = pos + (size_t)b * NPB * 3;

    for (int i = tid; i < NPB * 3; i += 1024) {
        float v = pb[i];
        int pt = i / 3, c = i - pt * 3;
        if (c == 0) spx[pt] = v; else if (c == 1) spy[pt] = v; else spz[pt] = v;
    }

    float4 wp0 = *(const float4*)(W1 + 64 * CDIM + 4 * lane);
    float4 wp1 = *(const float4*)(W1 + 65 * CDIM + 4 * lane);
    float4 wp2 = *(const float4*)(W1 + 66 * CDIM + 4 * lane);
    float4 bb  = *(const float4*)(b1 + 4 * lane);
    __syncthreads();

    unsigned long long* mykey = skey + warp * CAP;
    int* mysel = ssel + warp * KNN;
    const unsigned ltmask = (1u << lane) - 1u;
    const int qbase = sub * 128 + warp * 4;

    for (int qi = 0; qi < 4; qi++) {
        int m = qbase + qi;
        int row = b * MQ + m;
        float qx = g_qpos[row * 3 + 0];
        float qy = g_qpos[row * 3 + 1];
        float qz = g_qpos[row * 3 + 2];
        unsigned long long nqx2 = pk2(-qx, -qx);
        unsigned long long nqy2 = pk2(-qy, -qy);
        unsigned long long nqz2 = pk2(-qz, -qz);

        // packed scan: 2 points per lane per iter (same IEEE contraction as ref)
        int cnt = 0;
        for (int t = 0; t < NPB / 64; t++) {
            int i0 = t * 64 + lane, i1 = i0 + 32;
            unsigned long long ppx = pk2(spx[i0], spx[i1]);
            unsigned long long ppy = pk2(spy[i0], spy[i1]);
            unsigned long long ppz = pk2(spz[i0], spz[i1]);
            unsigned long long dx, dy, dz, d2p;
            ADD2(dx, ppx, nqx2);
            ADD2(dy, ppy, nqy2);
            ADD2(dz, ppz, nqz2);
            MUL2(d2p, dx, dx);
            FMA2(d2p, dy, dy, d2p);
            FMA2(d2p, dz, dz, d2p);
            float d2a, d2b; upk2(d2a, d2b, d2p);
            bool in0 = (d2a <= R2C), in1 = (d2b <= R2C);
            unsigned mk0 = __ballot_sync(FULLM, in0);
            unsigned mk1 = __ballot_sync(FULLM, in1);
            if (in0) {
                int off = cnt + __popc(mk0 & ltmask);
                if (off < CAP)
                    mykey[off] = ((unsigned long long)__float_as_uint(d2a) << 32) | (unsigned)i0;
            }
            cnt += __popc(mk0);
            if (in1) {
                int off = cnt + __popc(mk1 & ltmask);
                if (off < CAP)
                    mykey[off] = ((unsigned long long)__float_as_uint(d2b) << 32) | (unsigned)i1;
            }
            cnt += __popc(mk1);
        }
        if (cnt > CAP) cnt = CAP;

        int nsel;
        if (cnt <= KNN) {
            nsel = cnt;
            if (lane < cnt) mysel[lane] = (int)(mykey[lane] & 0xffffffffull);
        } else {
            nsel = KNN;
            int written = 0;
            for (int base = 0; base < cnt; base += 32) {
                int c = base + lane;
                bool s = false;
                unsigned long long ka = 0ull;
                if (c < cnt) {
                    ka = mykey[c];
                    int rank = 0;
                    for (int e = 0; e < cnt; e++) rank += (mykey[e] < ka) ? 1 : 0;
                    s = (rank < KNN);
                }
                unsigned mk = __ballot_sync(FULLM, s);
                if (s) mysel[written + __popc(mk & ltmask)] = (int)(ka & 0xffffffffull);
                written += __popc(mk);
            }
        }
        __syncwarp();

        float4 vm = make_float4(-3.4e38f, -3.4e38f, -3.4e38f, -3.4e38f);
        for (int s = 0; s < nsel; s++) {
            int j = mysel[s];
            float dx = spx[j] - qx, dy = spy[j] - qy, dz = spz[j] - qz;
            float4 xw = *(const float4*)(g_xw + (size_t)(b * NPB + j) * CDIM + 4 * lane);
            float v0 = fmaf(dz, wp2.x, fmaf(dy, wp1.x, fmaf(dx, wp0.x, xw.x)));
            float v1 = fmaf(dz, wp2.y, fmaf(dy, wp1.y, fmaf(dx, wp0.y, xw.y)));
            float v2 = fmaf(dz, wp2.z, fmaf(dy, wp1.z, fmaf(dx, wp0.z, xw.z)));
            float v3 = fmaf(dz, wp2.w, fmaf(dy, wp1.w, fmaf(dx, wp0.w, xw.w)));
            vm.x = fmaxf(vm.x, v0); vm.y = fmaxf(vm.y, v1);
            vm.z = fmaxf(vm.z, v2); vm.w = fmaxf(vm.w, v3);
        }
        float4 o;
        o.x = fmaxf(vm.x + bb.x, 0.0f);
        o.y = fmaxf(vm.y + bb.y, 0.0f);
        o.z = fmaxf(vm.z + bb.z, 0.0f);
        o.w = fmaxf(vm.w + bb.w, 0.0f);
        *(float4*)(dout + (size_t)row * CDIM + 4 * lane) = o;
        __syncwarp();
    }
}

// ------------------------------------------------------------------
extern "C" void kernel_launch(void* const* d_in, const int* in_sizes, int n_in,
                              void* d_out, int out_size)
{
    const float *x = nullptr, *pos = nullptr, *W1 = nullptr, *b1 = nullptr;
    for (int i = 0; i < n_in; i++) {
        switch (in_sizes[i]) {
            case NROWS * FDIM:      x   = (const float*)d_in[i]; break;
            case NROWS * 3:         pos = (const float*)d_in[i]; break;
            case (FDIM + 3) * CDIM: W1  = (const float*)d_in[i]; break;
            case CDIM:              b1  = (const float*)d_in[i]; break;
            default: break;                                        // batch (unused)
        }
    }
    float* out = (float*)d_out;
    long long total = (long long)NB * MQ * CDIM + (long long)NB * MQ * 3 + 2ll * NB * MQ;
    int extras = ((long long)out_size >= total) ? 1 : 0;

    size_t smem1 = (size_t)3 * NPB * 4 + 16 * 8;                   // positions + 2x8 u64 slots
    cudaFuncSetAttribute(fps_xw_kernel, cudaFuncAttributeMaxDynamicSharedMemorySize, (int)smem1);
    fps_xw_kernel<<<NB + 128, FPST, smem1>>>(pos, x, W1, out, extras);

    // 96KB positions + 64KB candidate keys (32 warps) + 4KB sel
    size_t smem2 = (size_t)3 * NPB * 4 + (size_t)32 * CAP * 8 + (size_t)32 * KNN * 4; // 167936
    cudaFuncSetAttribute(ballconv_kernel, cudaFuncAttributeMaxDynamicSharedMemorySize, (int)smem2);
    ballconv_kernel<<<128, 1024, smem2>>>(pos, W1, b1, out);
}